// round 15
// baseline (speedup 1.0000x reference)
#include <cuda_runtime.h>
#include <cuda_fp16.h>
#include <math.h>
#include <stdint.h>

// ----------------------------------------------------------------------------
// Shapes (fixed)
// ----------------------------------------------------------------------------
#define B_   4
#define L_   1024
#define D_   1024
#define H_   16
#define HD_  64
#define FF_  4096
#define NS_  64
#define M_   (B_ * L_)          // 4096 rows

// ----------------------------------------------------------------------------
// Scratch (bytes) — single fp16 plane per tensor
// ----------------------------------------------------------------------------
#define SZ_WQKV   (3072ull*1024u*2u)
#define SZ_WO     (1024ull*1024u*2u)
#define SZ_WF1    (8192ull*1024u*2u)
#define SZ_WF2    (1024ull*4096u*2u)
#define SZ_ACT    (4096ull*1024u*2u)
#define SZ_KVN    (256ull*1024u*2u)
#define SZ_GG     (4096ull*4096u*2u)
#define SZ_QKV1   (4096ull*3072u*2u)
#define SZ_CKV1   (256ull*2048u*2u)
#define SZ_D32    (4096ull*1024u*4u)
#define SZ_ALIBI  (64ull*1024u*1024u*2u)   // B*H*L*L fp16 = 128 MB

#define O_WQKVS     0ull
#define O_WSAO      (O_WQKVS + SZ_WQKV)
#define O_WQKVC     (O_WSAO + SZ_WO)
#define O_WCAO      (O_WQKVC + SZ_WQKV)
#define O_WF1       (O_WCAO + SZ_WO)
#define O_WF2       (O_WF1 + SZ_WF1)
#define O_LN        (O_WF2 + SZ_WF2)
#define O_AT        (O_LN + SZ_ACT)
#define O_KVN       (O_AT + SZ_ACT)
#define O_GG        (O_KVN + SZ_KVN)
#define O_QKV       (O_GG + SZ_GG)
#define O_CQ        (O_QKV + SZ_QKV1)
#define O_CKV       (O_CQ + SZ_ACT)
#define O_X1        (O_CKV + SZ_CKV1)
#define O_X2        (O_X1 + SZ_D32)
#define O_ALIBI     (O_X2 + SZ_D32)
#define SCRATCH_BYTES (O_ALIBI + SZ_ALIBI)

__device__ __align__(1024) char g_scratch[SCRATCH_BYTES];

// ----------------------------------------------------------------------------
// PTX helpers (family-agnostic)
// ----------------------------------------------------------------------------
__device__ __forceinline__ uint32_t smem_u32(const void* p) {
    uint32_t a;
    asm("{ .reg .u64 t; cvta.to.shared.u64 t, %1; cvt.u32.u64 %0, t; }"
        : "=r"(a) : "l"(p));
    return a;
}
__device__ __forceinline__ void cpa16(uint32_t s, const void* g) {
    asm volatile("cp.async.cg.shared.global [%0], [%1], 16;" :: "r"(s), "l"(g));
}
#define CP_COMMIT() asm volatile("cp.async.commit_group;" ::: "memory")
#define CP_WAIT0() asm volatile("cp.async.wait_group 0;" ::: "memory")
#define CP_WAIT1() asm volatile("cp.async.wait_group 1;" ::: "memory")
#define CP_WAIT2() asm volatile("cp.async.wait_group 2;" ::: "memory")

__device__ __forceinline__ void ldm_x4(uint32_t* r, uint32_t addr) {
    asm volatile("ldmatrix.sync.aligned.m8n8.x4.shared.b16 {%0,%1,%2,%3}, [%4];"
        : "=r"(r[0]), "=r"(r[1]), "=r"(r[2]), "=r"(r[3]) : "r"(addr));
}
__device__ __forceinline__ void ldm_x4_t(uint32_t* r, uint32_t addr) {
    asm volatile("ldmatrix.sync.aligned.m8n8.x4.trans.shared.b16 {%0,%1,%2,%3}, [%4];"
        : "=r"(r[0]), "=r"(r[1]), "=r"(r[2]), "=r"(r[3]) : "r"(addr));
}
__device__ __forceinline__ void mma_f16(float* d, const uint32_t* a, const uint32_t* b) {
    asm volatile(
        "mma.sync.aligned.m16n8k16.row.col.f32.f16.f16.f32 "
        "{%0,%1,%2,%3}, {%4,%5,%6,%7}, {%8,%9}, {%0,%1,%2,%3};"
        : "+f"(d[0]), "+f"(d[1]), "+f"(d[2]), "+f"(d[3])
        : "r"(a[0]), "r"(a[1]), "r"(a[2]), "r"(a[3]), "r"(b[0]), "r"(b[1]));
}

__device__ __forceinline__ __half2 packh(float a, float b) {
    return __floats2half2_rn(a, b);
}
__device__ __forceinline__ uint32_t packu(float a, float b) {
    __half2 v = packh(a, b);
    return *(uint32_t*)&v;
}

// Fast exp on FFMA pipe (x <= 0 path), rel err ~2e-6
__device__ __forceinline__ float fexp(float x) {
    float z = x * 1.4426950408889634f;
    z = fmaxf(z, -120.0f);
    float zi = z + 12582912.0f;
    int i = __float_as_int(zi) - 0x4B400000;
    float f = z - (zi - 12582912.0f);
    float p = 1.3333558e-3f;
    p = fmaf(p, f, 9.6181291e-3f);
    p = fmaf(p, f, 5.5504109e-2f);
    p = fmaf(p, f, 2.4022651e-1f);
    p = fmaf(p, f, 6.9314718e-1f);
    p = fmaf(p, f, 1.0f);
    return p * __int_as_float((i + 127) << 23);
}

// ----------------------------------------------------------------------------
// Convert: fp32 -> fp16 (weights, alibi)
// ----------------------------------------------------------------------------
__global__ __launch_bounds__(256)
void cvt_h_kernel(const float4* __restrict__ w, __half2* __restrict__ hi, int n4) {
    int i = blockIdx.x * 256 + threadIdx.x;
    if (i >= n4) return;
    const float4 v = w[i];
    hi[i * 2]     = packh(v.x, v.y);
    hi[i * 2 + 1] = packh(v.z, v.w);
}

// ffn_w1 interleave: dst row 2j = w1[j] (val), 2j+1 = w1[FF+j] (gate)
__global__ __launch_bounds__(256)
void cvt_h_ileave_kernel(const float* __restrict__ w, __half2* __restrict__ hi, int n4) {
    int i = blockIdx.x * 256 + threadIdx.x;
    if (i >= n4) return;
    const int row = i >> 8;
    const int col4 = (i & 255) * 4;
    const int srow = (row & 1) ? (FF_ + (row >> 1)) : (row >> 1);
    const float4 v = *(const float4*)(w + (size_t)srow * 1024 + col4);
    hi[i * 2]     = packh(v.x, v.y);
    hi[i * 2 + 1] = packh(v.z, v.w);
}

// ----------------------------------------------------------------------------
// LayerNorm -> fp16 plane
// ----------------------------------------------------------------------------
__global__ __launch_bounds__(256)
void ln_kernel(const float* __restrict__ x, const float* __restrict__ g,
               const float* __restrict__ b, __half* __restrict__ yh) {
    const int row = blockIdx.x;
    const int t = threadIdx.x;
    const float4 v = ((const float4*)(x + (size_t)row * D_))[t];

    __shared__ float red[8];
    __shared__ float stat[2];

    float s = v.x + v.y + v.z + v.w;
    #pragma unroll
    for (int o = 16; o; o >>= 1) s += __shfl_xor_sync(0xffffffffu, s, o);
    if ((t & 31) == 0) red[t >> 5] = s;
    __syncthreads();
    if (t == 0) {
        float s2 = 0.f;
        #pragma unroll
        for (int i = 0; i < 8; i++) s2 += red[i];
        stat[0] = s2 * (1.0f / D_);
    }
    __syncthreads();
    const float mu = stat[0];
    const float dx = v.x - mu, dy = v.y - mu, dz = v.z - mu, dw = v.w - mu;

    float q = dx * dx + dy * dy + dz * dz + dw * dw;
    #pragma unroll
    for (int o = 16; o; o >>= 1) q += __shfl_xor_sync(0xffffffffu, q, o);
    if ((t & 31) == 0) red[t >> 5] = q;
    __syncthreads();
    if (t == 0) {
        float s2 = 0.f;
        #pragma unroll
        for (int i = 0; i < 8; i++) s2 += red[i];
        stat[1] = rsqrtf(s2 * (1.0f / D_) + 1e-5f);
    }
    __syncthreads();
    const float rs = stat[1];

    const float4 gv = ((const float4*)g)[t];
    const float4 bv = ((const float4*)b)[t];
    const float o0 = dx * rs * gv.x + bv.x;
    const float o1 = dy * rs * gv.y + bv.y;
    const float o2 = dz * rs * gv.z + bv.z;
    const float o3 = dw * rs * gv.w + bv.w;
    const size_t base = (size_t)row * D_ + t * 4;
    *(__half2*)(yh + base)     = packh(o0, o1);
    *(__half2*)(yh + base + 2) = packh(o2, o3);
}

__device__ __forceinline__ float gelu_exact(float x) {
    return 0.5f * x * (1.0f + erff(x * 0.7071067811865476f));
}

// ----------------------------------------------------------------------------
// mma.sync 1-term fp16 GEMM: C[M,N] = A[M,K] @ W[N,K]^T (+epilogue)
// CTA tile 128x256, warp tile 64x64 (2x4 warps), K-chunk 64, 3-stage cp.async,
// register-fragment double buffering.
// EPI: 1 bias+res (fp32 out); 2 sigmoid(gate)*(..)+res (fp32 out);
//      3 bias only -> fp16 plane; 4 GEGLU (interleaved W) -> fp16 plane
// ----------------------------------------------------------------------------
#define TM 128
#define TN 256
#define KCH 64
#define RS 72
#define RSB (RS * 2)
#define APLANE_B (128 * RSB)        // 18432
#define WPLANE_B (256 * RSB)        // 36864
#define SA_A 0
#define SW_W APLANE_B
#define STAGE_B (APLANE_B + WPLANE_B)  // 55296
#define GEMM_SMEM (3 * STAGE_B)        // 165888

template <int EPI>
__global__ __launch_bounds__(256, 1)
void mma_gemm(const __half* __restrict__ A, const __half* __restrict__ W,
              const float* __restrict__ bias, const float* __restrict__ res,
              const float* __restrict__ gatep, float* __restrict__ C,
              __half* __restrict__ Ch,
              int N, int K, int wRowOff) {
    extern __shared__ char smem[];
    const uint32_t sb = smem_u32(smem);
    const int t = threadIdx.x;
    const int lane = t & 31;
    const int wid = t >> 5;
    const int wm = wid & 1;         // m half (64)
    const int wn = wid >> 1;        // n quarter (64)

    const int mBase = blockIdx.y * TM;
    const int nBase = blockIdx.x * TN;

    uint32_t sOffA[4], sOffW[8];
    size_t gOffA[4], gOffW[8];
    #pragma unroll
    for (int j = 0; j < 4; j++) {
        const int id = t + 256 * j;
        const int r = id >> 3;
        const int ch = id & 7;
        sOffA[j] = (uint32_t)r * RSB + ch * 16;
        gOffA[j] = ((size_t)(mBase + r) * K + ch * 8) * 2;
    }
    #pragma unroll
    for (int j = 0; j < 8; j++) {
        const int id = t + 256 * j;
        const int r = id >> 3;
        const int ch = id & 7;
        sOffW[j] = (uint32_t)r * RSB + ch * 16;
        gOffW[j] = ((size_t)(nBase + wRowOff + r) * K + ch * 8) * 2;
    }
    const char* pA = (const char*)A;
    const char* pW = (const char*)W;

    auto load_stage = [&](int c, int s) {
        const uint32_t sd = sb + s * STAGE_B;
        const size_t kb = (size_t)c * 128;
        #pragma unroll
        for (int j = 0; j < 4; j++)
            cpa16(sd + SA_A + sOffA[j], pA + gOffA[j] + kb);
        #pragma unroll
        for (int j = 0; j < 8; j++)
            cpa16(sd + SW_W + sOffW[j], pW + gOffW[j] + kb);
    };

    float acc[4][8][4];
    #pragma unroll
    for (int i = 0; i < 4; i++)
        #pragma unroll
        for (int j = 0; j < 8; j++)
            #pragma unroll
            for (int k = 0; k < 4; k++) acc[i][j][k] = 0.f;

    const int nch = K / KCH;
    load_stage(0, 0); CP_COMMIT();
    if (nch > 1) { load_stage(1, 1); CP_COMMIT(); }

    const uint32_t aRowOff = (uint32_t)(wm * 64 + (lane & 15)) * RSB
                           + ((lane >> 4) * 8) * 2;
    const uint32_t bRowOff = (uint32_t)(wn * 64 + (lane & 7) + ((lane >> 4) & 1) * 8) * RSB
                           + (((lane >> 3) & 1) * 8) * 2;

    uint32_t ah[2][4][4];
    uint32_t bw[2][8][2];

    int sidx = 0;
    for (int c = 0; c < nch; c++) {
        if (c + 2 < nch) {
            load_stage(c + 2, (sidx + 2) % 3);
            CP_COMMIT();
            CP_WAIT2();
        } else if (c + 1 < nch) {
            CP_WAIT1();
        } else {
            CP_WAIT0();
        }
        __syncthreads();

        const uint32_t sd = sb + sidx * STAGE_B;

        auto load_frags = [&](int kk, int buf) {
            #pragma unroll
            for (int mf = 0; mf < 4; mf++) {
                const uint32_t ad = sd + SA_A + aRowOff + (uint32_t)(mf * 16) * RSB + kk * 2;
                ldm_x4(ah[buf][mf], ad);
            }
            #pragma unroll
            for (int nf2 = 0; nf2 < 4; nf2++) {
                const uint32_t bd = sd + SW_W + bRowOff + (uint32_t)(nf2 * 16) * RSB + kk * 2;
                uint32_t r[4];
                ldm_x4(r, bd);
                bw[buf][nf2 * 2][0] = r[0]; bw[buf][nf2 * 2][1] = r[1];
                bw[buf][nf2 * 2 + 1][0] = r[2]; bw[buf][nf2 * 2 + 1][1] = r[3];
            }
        };

        load_frags(0, 0);
        #pragma unroll
        for (int s16 = 0; s16 < KCH / 16; s16++) {
            if (s16 + 1 < KCH / 16) load_frags((s16 + 1) * 16, (s16 + 1) & 1);
            const int buf = s16 & 1;
            #pragma unroll
            for (int mf = 0; mf < 4; mf++)
                #pragma unroll
                for (int nf = 0; nf < 8; nf++)
                    mma_f16(acc[mf][nf], ah[buf][mf], bw[buf][nf]);
        }
        __syncthreads();
        sidx = (sidx + 1) % 3;
    }

    // ---- epilogue ----
    float gs = 1.f;
    if (EPI == 2) gs = 1.f / (1.f + __expf(-gatep[0]));

    const int mWarp = mBase + wm * 64;
    const int nWarp = nBase + wn * 64;
    #pragma unroll
    for (int mf = 0; mf < 4; mf++) {
        const int r0 = mWarp + mf * 16 + (lane >> 2);
        #pragma unroll
        for (int nf = 0; nf < 8; nf++) {
            const int c0 = nWarp + nf * 8 + 2 * (lane & 3);
            if (EPI == 1 || EPI == 2) {
                const float b0 = bias[c0], b1 = bias[c0 + 1];
                float v0 = acc[mf][nf][0] + b0;
                float v1 = acc[mf][nf][1] + b1;
                float v2 = acc[mf][nf][2] + b0;
                float v3 = acc[mf][nf][3] + b1;
                if (EPI == 1) {
                    v0 += res[(size_t)r0 * N + c0];
                    v1 += res[(size_t)r0 * N + c0 + 1];
                    v2 += res[(size_t)(r0 + 8) * N + c0];
                    v3 += res[(size_t)(r0 + 8) * N + c0 + 1];
                } else {
                    v0 = gs * v0 + res[(size_t)r0 * N + c0];
                    v1 = gs * v1 + res[(size_t)r0 * N + c0 + 1];
                    v2 = gs * v2 + res[(size_t)(r0 + 8) * N + c0];
                    v3 = gs * v3 + res[(size_t)(r0 + 8) * N + c0 + 1];
                }
                *(float2*)(C + (size_t)r0 * N + c0) = make_float2(v0, v1);
                *(float2*)(C + (size_t)(r0 + 8) * N + c0) = make_float2(v2, v3);
            } else if (EPI == 3) {
                const float b0 = bias[c0], b1 = bias[c0 + 1];
                *(__half2*)(Ch + (size_t)r0 * N + c0) =
                    packh(acc[mf][nf][0] + b0, acc[mf][nf][1] + b1);
                *(__half2*)(Ch + (size_t)(r0 + 8) * N + c0) =
                    packh(acc[mf][nf][2] + b0, acc[mf][nf][3] + b1);
            } else {  // EPI == 4: GEGLU with interleaved W (even=val, odd=gate)
                const int jj = c0 >> 1;
                const int Nout = N >> 1;
                const float bv = bias[jj], bg = bias[FF_ + jj];
                const float va = acc[mf][nf][0] + bv;
                const float ga = acc[mf][nf][1] + bg;
                const float vb = acc[mf][nf][2] + bv;
                const float gb = acc[mf][nf][3] + bg;
                Ch[(size_t)r0 * Nout + jj] = __float2half_rn(va * gelu_exact(ga));
                Ch[(size_t)(r0 + 8) * Nout + jj] = __float2half_rn(vb * gelu_exact(gb));
            }
        }
    }
}

// ----------------------------------------------------------------------------
// Tensor-core flash attention (1-term fp16), HD=64, 64q x 64kv tiles.
// 128 threads (4 warps); warp w owns q rows [16w,16w+16).
// bias (optional) is fp16. Output fp16 plane with row stride D_.
// ----------------------------------------------------------------------------
#define FRSB 144
#define FPLANE (64 * FRSB)            // 9216
#define FSTAGE (2 * FPLANE)           // 18432 (K, V)
#define FQOFF  (2 * FSTAGE)           // 36864 (Q)
#define FLASH_SMEM (FQOFF + FPLANE)   // 46080

__global__ __launch_bounds__(128)
void flash_mma(const __half* __restrict__ Qh, int ldq,
               const __half* __restrict__ Kh, int ldk,
               const __half* __restrict__ Vh,
               const __half* __restrict__ bias,
               __half* __restrict__ Oh,
               int Lq, int Lkv) {
    extern __shared__ char smem[];
    const uint32_t sb = smem_u32(smem);
    const int t = threadIdx.x, lane = t & 31, w = t >> 5;
    const int bh = blockIdx.y, b = bh >> 4, h = bh & 15;
    const int q0 = blockIdx.x * 64;

    // Q tile -> smem
    #pragma unroll
    for (int j = 0; j < 4; j++) {
        const int id = t + 128 * j, r = id >> 3, ch = id & 7;
        const size_t g = ((size_t)(b * Lq + q0 + r)) * ldq + h * 64 + ch * 8;
        cpa16(sb + FQOFF + (uint32_t)r * FRSB + ch * 16, (const char*)Qh + g * 2);
    }
    CP_COMMIT();

    auto load_kv = [&](int it, int s) {
        const uint32_t sd = sb + s * FSTAGE;
        const int k0 = it * 64;
        #pragma unroll
        for (int j = 0; j < 4; j++) {
            const int id = t + 128 * j, r = id >> 3, ch = id & 7;
            const size_t g = ((size_t)(b * Lkv + k0 + r)) * ldk + h * 64 + ch * 8;
            const uint32_t so = sd + (uint32_t)r * FRSB + ch * 16;
            cpa16(so,          (const char*)Kh + g * 2);
            cpa16(so + FPLANE, (const char*)Vh + g * 2);
        }
    };
    load_kv(0, 0); CP_COMMIT();

    uint32_t qf[4][4];
    float o_[8][4];
    #pragma unroll
    for (int i = 0; i < 8; i++)
        #pragma unroll
        for (int j = 0; j < 4; j++) o_[i][j] = 0.f;
    float m0 = -1e30f, m1 = -1e30f, l0 = 0.f, l1 = 0.f;
    const float invs = 0.125f;

    const int nt = Lkv / 64;
    for (int it = 0; it < nt; it++) {
        if (it + 1 < nt) { load_kv(it + 1, (it + 1) & 1); CP_COMMIT(); CP_WAIT1(); }
        else { CP_WAIT0(); }
        __syncthreads();
        const uint32_t sd = sb + (it & 1) * FSTAGE;

        if (it == 0) {
            #pragma unroll
            for (int kf = 0; kf < 4; kf++) {
                const uint32_t qa = sb + FQOFF
                    + (uint32_t)(w * 16 + (lane & 15)) * FRSB
                    + ((lane >> 4) * 8 + kf * 16) * 2;
                ldm_x4(qf[kf], qa);
            }
        }

        // ---- S = Q K^T ----
        float s_[8][4];
        #pragma unroll
        for (int i = 0; i < 8; i++)
            #pragma unroll
            for (int j = 0; j < 4; j++) s_[i][j] = 0.f;
        #pragma unroll
        for (int kf = 0; kf < 4; kf++) {
            #pragma unroll
            for (int g = 0; g < 4; g++) {
                const uint32_t ka = sd
                    + (uint32_t)(g * 16 + (lane & 7) + ((lane >> 4) & 1) * 8) * FRSB
                    + (((lane >> 3) & 1) * 8 + kf * 16) * 2;
                uint32_t rh[4];
                ldm_x4(rh, ka);
                mma_f16(s_[2 * g],     qf[kf], rh);
                mma_f16(s_[2 * g + 1], qf[kf], rh + 2);
            }
        }

        // ---- scale + bias (fp16 bias) ----
        if (bias) {
            const int k0 = it * 64;
            const __half* bp = bias
                + ((size_t)bh * Lq + (q0 + w * 16 + (lane >> 2))) * Lkv
                + k0 + (lane & 3) * 2;
            #pragma unroll
            for (int nf = 0; nf < 8; nf++) {
                const float2 b0 = __half22float2(*(const __half2*)(bp + nf * 8));
                const float2 b1 = __half22float2(*(const __half2*)(bp + (size_t)8 * Lkv + nf * 8));
                s_[nf][0] = fmaf(s_[nf][0], invs, b0.x);
                s_[nf][1] = fmaf(s_[nf][1], invs, b0.y);
                s_[nf][2] = fmaf(s_[nf][2], invs, b1.x);
                s_[nf][3] = fmaf(s_[nf][3], invs, b1.y);
            }
        } else {
            #pragma unroll
            for (int nf = 0; nf < 8; nf++)
                #pragma unroll
                for (int i = 0; i < 4; i++) s_[nf][i] *= invs;
        }

        // ---- online softmax ----
        float mx0 = s_[0][0], mx1 = s_[0][2];
        #pragma unroll
        for (int nf = 0; nf < 8; nf++) {
            mx0 = fmaxf(mx0, fmaxf(s_[nf][0], s_[nf][1]));
            mx1 = fmaxf(mx1, fmaxf(s_[nf][2], s_[nf][3]));
        }
        mx0 = fmaxf(mx0, __shfl_xor_sync(0xffffffffu, mx0, 1));
        mx0 = fmaxf(mx0, __shfl_xor_sync(0xffffffffu, mx0, 2));
        mx1 = fmaxf(mx1, __shfl_xor_sync(0xffffffffu, mx1, 1));
        mx1 = fmaxf(mx1, __shfl_xor_sync(0xffffffffu, mx1, 2));
        const float mn0 = fmaxf(m0, mx0), mn1 = fmaxf(m1, mx1);
        const float sc0 = fexp(m0 - mn0), sc1 = fexp(m1 - mn1);
        m0 = mn0; m1 = mn1;
        float sum0 = 0.f, sum1 = 0.f;
        #pragma unroll
        for (int nf = 0; nf < 8; nf++) {
            s_[nf][0] = fexp(s_[nf][0] - mn0);
            s_[nf][1] = fexp(s_[nf][1] - mn0);
            s_[nf][2] = fexp(s_[nf][2] - mn1);
            s_[nf][3] = fexp(s_[nf][3] - mn1);
            sum0 += s_[nf][0] + s_[nf][1];
            sum1 += s_[nf][2] + s_[nf][3];
        }
        sum0 += __shfl_xor_sync(0xffffffffu, sum0, 1);
        sum0 += __shfl_xor_sync(0xffffffffu, sum0, 2);
        sum1 += __shfl_xor_sync(0xffffffffu, sum1, 1);
        sum1 += __shfl_xor_sync(0xffffffffu, sum1, 2);
        l0 = l0 * sc0 + sum0;
        l1 = l1 * sc1 + sum1;
        #pragma unroll
        for (int nf = 0; nf < 8; nf++) {
            o_[nf][0] *= sc0; o_[nf][1] *= sc0;
            o_[nf][2] *= sc1; o_[nf][3] *= sc1;
        }

        // ---- O += P V (P from regs, V via ldmatrix.trans) ----
        #pragma unroll
        for (int kf = 0; kf < 4; kf++) {
            uint32_t pa[4];
            pa[0] = packu(s_[2 * kf][0], s_[2 * kf][1]);
            pa[1] = packu(s_[2 * kf][2], s_[2 * kf][3]);
            pa[2] = packu(s_[2 * kf + 1][0], s_[2 * kf + 1][1]);
            pa[3] = packu(s_[2 * kf + 1][2], s_[2 * kf + 1][3]);
            #pragma unroll
            for (int g = 0; g < 4; g++) {
                const uint32_t va = sd + FPLANE
                    + (uint32_t)(kf * 16 + (lane & 15)) * FRSB
                    + ((lane >> 4) * 8 + g * 16) * 2;
                uint32_t rh[4];
                ldm_x4_t(rh, va);
                mma_f16(o_[2 * g],     pa, rh);
                mma_f16(o_[2 * g + 1], pa, rh + 2);
            }
        }
        __syncthreads();
    }

    // ---- normalize + store fp16 ----
    const float inv0 = 1.f / l0, inv1 = 1.f / l1;
    const int row0 = b * Lq + q0 + w * 16 + (lane >> 2);
    #pragma unroll
    for (int nf = 0; nf < 8; nf++) {
        const int col = h * 64 + nf * 8 + (lane & 3) * 2;
        *(__half2*)(Oh + (size_t)row0 * D_ + col) =
            packh(o_[nf][0] * inv0, o_[nf][1] * inv0);
        *(__half2*)(Oh + (size_t)(row0 + 8) * D_ + col) =
            packh(o_[nf][2] * inv1, o_[nf][3] * inv1);
    }
}

// ----------------------------------------------------------------------------
// Host orchestration — stream-fork overlap (graph-capturable fork/join).
// ----------------------------------------------------------------------------
extern "C" void kernel_launch(void* const* d_in, const int* in_sizes, int n_in,
                              void* d_out, int out_size) {
    const float* x          = (const float*)d_in[0];
    const float* alibi      = (const float*)d_in[1];
    const float* species    = (const float*)d_in[2];
    const float* norm1_g    = (const float*)d_in[3];
    const float* norm1_b    = (const float*)d_in[4];
    const float* sa_wqkv    = (const float*)d_in[5];
    const float* sa_bqkv    = (const float*)d_in[6];
    const float* sa_wo      = (const float*)d_in[7];
    const float* sa_bo      = (const float*)d_in[8];
    const float* ca_nq_g    = (const float*)d_in[9];
    const float* ca_nq_b    = (const float*)d_in[10];
    const float* ca_nkv_g   = (const float*)d_in[11];
    const float* ca_nkv_b   = (const float*)d_in[12];
    const float* ca_wqkv    = (const float*)d_in[13];
    const float* ca_bqkv    = (const float*)d_in[14];
    const float* ca_wo      = (const float*)d_in[15];
    const float* ca_bo      = (const float*)d_in[16];
    const float* gate_param = (const float*)d_in[17];
    const float* ffn_g      = (const float*)d_in[18];
    const float* ffn_b      = (const float*)d_in[19];
    const float* ffn_w1     = (const float*)d_in[20];
    const float* ffn_b1     = (const float*)d_in[21];
    const float* ffn_w2     = (const float*)d_in[22];
    const float* ffn_b2     = (const float*)d_in[23];
    float* out = (float*)d_out;

    char* S = nullptr;
    cudaGetSymbolAddress((void**)&S, g_scratch);
    #define HF(off) ((__half*)(S + (off)))
    #define F32(off) ((float*)(S + (off)))
    __half *wqkvs = HF(O_WQKVS), *wsao = HF(O_WSAO);
    __half *wqkvc = HF(O_WQKVC), *wcao = HF(O_WCAO);
    __half *wf1 = HF(O_WF1), *wf2 = HF(O_WF2);
    __half *lnb = HF(O_LN), *atb = HF(O_AT), *kvnb = HF(O_KVN);
    __half *ggb = HF(O_GG), *qkvb = HF(O_QKV);
    __half *cqb = HF(O_CQ), *ckvb = HF(O_CKV);
    __half *al16 = HF(O_ALIBI);
    float *x1 = F32(O_X1), *x2 = F32(O_X2);

    cudaFuncSetAttribute(mma_gemm<1>, cudaFuncAttributeMaxDynamicSharedMemorySize, GEMM_SMEM);
    cudaFuncSetAttribute(mma_gemm<2>, cudaFuncAttributeMaxDynamicSharedMemorySize, GEMM_SMEM);
    cudaFuncSetAttribute(mma_gemm<3>, cudaFuncAttributeMaxDynamicSharedMemorySize, GEMM_SMEM);
    cudaFuncSetAttribute(mma_gemm<4>, cudaFuncAttributeMaxDynamicSharedMemorySize, GEMM_SMEM);
    cudaFuncSetAttribute(flash_mma, cudaFuncAttributeMaxDynamicSharedMemorySize, FLASH_SMEM);

    cudaStream_t sA, sB;
    cudaStreamCreateWithFlags(&sA, cudaStreamNonBlocking);
    cudaStreamCreateWithFlags(&sB, cudaStreamNonBlocking);
    cudaEvent_t evFork, evQ, evW, evF, evB, evC, evAL;
    cudaEventCreateWithFlags(&evFork, cudaEventDisableTiming);
    cudaEventCreateWithFlags(&evQ,    cudaEventDisableTiming);
    cudaEventCreateWithFlags(&evW,    cudaEventDisableTiming);
    cudaEventCreateWithFlags(&evF,    cudaEventDisableTiming);
    cudaEventCreateWithFlags(&evB,    cudaEventDisableTiming);
    cudaEventCreateWithFlags(&evC,    cudaEventDisableTiming);
    cudaEventCreateWithFlags(&evAL,   cudaEventDisableTiming);

    auto cvt_on = [&](cudaStream_t st, const float* w, __half* h, size_t n) {
        cvt_h_kernel<<<(unsigned)((n / 4 + 255) / 256), 256, 0, st>>>(
            (const float4*)w, (__half2*)h, (int)(n / 4));
    };

    // ---- fork ----
    cudaEventRecord(evFork, 0);
    cudaStreamWaitEvent(sA, evFork, 0);
    cudaStreamWaitEvent(sB, evFork, 0);

    // side stream B: alibi fp32 -> fp16 (hidden under QKV GEMM)
    cvt_on(sB, alibi, al16, (size_t)B_ * H_ * L_ * L_);
    cudaEventRecord(evAL, sB);

    // side stream A: QKV weights first (joined before QKV GEMM), then the rest
    cvt_on(sA, sa_wqkv, wqkvs, (size_t)3 * D_ * D_);
    cudaEventRecord(evQ, sA);
    cvt_on(sA, sa_wo,   wsao,  (size_t)D_ * D_);
    cvt_on(sA, ca_wqkv, wqkvc, (size_t)3 * D_ * D_);
    cvt_on(sA, ca_wo,   wcao,  (size_t)D_ * D_);
    ln_kernel<<<B_ * NS_, 256, 0, sA>>>(species, ca_nkv_g, ca_nkv_b, kvnb);
    cudaEventRecord(evW, sA);           // joined before SA-out GEMM
    cvt_on(sA, ffn_w2, wf2, (size_t)D_ * FF_);
    cvt_h_ileave_kernel<<<(2 * FF_ * D_ / 4 + 255) / 256, 256, 0, sA>>>(
        ffn_w1, (__half2*)wf1, 2 * FF_ * D_ / 4);
    cudaEventRecord(evF, sA);           // joined before FFN1 GEMM

    // ---- main stream: self-attention ----
    ln_kernel<<<M_, 256>>>(x, norm1_g, norm1_b, lnb);
    cudaStreamWaitEvent(0, evQ, 0);
    mma_gemm<3><<<dim3(3 * D_ / TN, M_ / TM), 256, GEMM_SMEM>>>(
        lnb, wqkvs, sa_bqkv, nullptr, nullptr, nullptr, qkvb, 3 * D_, D_, 0);
    cudaStreamWaitEvent(0, evAL, 0);    // fp16 alibi ready
    flash_mma<<<dim3(L_ / 64, B_ * H_), 128, FLASH_SMEM>>>(
        qkvb, 3 * D_,
        qkvb + D_, 3 * D_,
        qkvb + 2 * D_,
        al16, atb, L_, L_);
    cudaStreamWaitEvent(0, evW, 0);     // wsao/wqkvc/wcao/kvnb ready
    mma_gemm<1><<<dim3(D_ / TN, M_ / TM), 256, GEMM_SMEM>>>(
        atb, wsao, sa_bo, x, nullptr, x1, nullptr, D_, D_, 0);

    // ---- cross-attention (ckv GEMM overlapped on stream B) ----
    ln_kernel<<<M_, 256>>>(x1, ca_nq_g, ca_nq_b, lnb);
    cudaEventRecord(evB, 0);
    cudaStreamWaitEvent(sB, evB, 0);
    mma_gemm<3><<<dim3(2 * D_ / TN, (B_ * NS_) / TM), 256, GEMM_SMEM, sB>>>(
        kvnb, wqkvc, ca_bqkv + D_, nullptr, nullptr, nullptr, ckvb, 2 * D_, D_, D_);
    cudaEventRecord(evC, sB);
    mma_gemm<3><<<dim3(D_ / TN, M_ / TM), 256, GEMM_SMEM>>>(
        lnb, wqkvc, ca_bqkv, nullptr, nullptr, nullptr, cqb, D_, D_, 0);
    cudaStreamWaitEvent(0, evC, 0);
    flash_mma<<<dim3(L_ / 64, B_ * H_), 128, FLASH_SMEM>>>(
        cqb, D_,
        ckvb, 2 * D_,
        ckvb + D_,
        nullptr, atb, L_, NS_);
    mma_gemm<2><<<dim3(D_ / TN, M_ / TM), 256, GEMM_SMEM>>>(
        atb, wcao, ca_bo, x1, gate_param, x2, nullptr, D_, D_, 0);

    // ---- FFN (GEGLU fused into FFN1 epilogue) ----
    ln_kernel<<<M_, 256>>>(x2, ffn_g, ffn_b, lnb);
    cudaStreamWaitEvent(0, evF, 0);     // wf1/wf2 ready
    mma_gemm<4><<<dim3(2 * FF_ / TN, M_ / TM), 256, GEMM_SMEM>>>(
        lnb, wf1, ffn_b1, nullptr, nullptr, nullptr, ggb, 2 * FF_, D_, 0);
    mma_gemm<1><<<dim3(D_ / TN, M_ / TM), 256, GEMM_SMEM>>>(
        ggb, wf2, ffn_b2, x2, nullptr, out, nullptr, D_, FF_, 0);

    cudaEventDestroy(evFork);
    cudaEventDestroy(evQ);
    cudaEventDestroy(evW);
    cudaEventDestroy(evF);
    cudaEventDestroy(evB);
    cudaEventDestroy(evC);
    cudaEventDestroy(evAL);
    cudaStreamDestroy(sA);
    cudaStreamDestroy(sB);
}

// round 16
// speedup vs baseline: 1.0835x; 1.0835x over previous
#include <cuda_runtime.h>
#include <cuda_fp16.h>
#include <math.h>
#include <stdint.h>

// ----------------------------------------------------------------------------
// Shapes (fixed)
// ----------------------------------------------------------------------------
#define B_   4
#define L_   1024
#define D_   1024
#define H_   16
#define HD_  64
#define FF_  4096
#define NS_  64
#define M_   (B_ * L_)          // 4096 rows

// ----------------------------------------------------------------------------
// Scratch (bytes) — single fp16 plane per tensor
// ----------------------------------------------------------------------------
#define SZ_WQKV   (3072ull*1024u*2u)
#define SZ_WO     (1024ull*1024u*2u)
#define SZ_WF1    (8192ull*1024u*2u)
#define SZ_WF2    (1024ull*4096u*2u)
#define SZ_ACT    (4096ull*1024u*2u)
#define SZ_KVN    (256ull*1024u*2u)
#define SZ_GG     (4096ull*4096u*2u)
#define SZ_QKV1   (4096ull*3072u*2u)
#define SZ_CKV1   (256ull*2048u*2u)
#define SZ_D32    (4096ull*1024u*4u)

#define O_WQKVS     0ull
#define O_WSAO      (O_WQKVS + SZ_WQKV)
#define O_WQKVC     (O_WSAO + SZ_WO)
#define O_WCAO      (O_WQKVC + SZ_WQKV)
#define O_WF1       (O_WCAO + SZ_WO)
#define O_WF2       (O_WF1 + SZ_WF1)
#define O_LN        (O_WF2 + SZ_WF2)
#define O_AT        (O_LN + SZ_ACT)
#define O_KVN       (O_AT + SZ_ACT)
#define O_GG        (O_KVN + SZ_KVN)
#define O_QKV       (O_GG + SZ_GG)
#define O_CQ        (O_QKV + SZ_QKV1)
#define O_CKV       (O_CQ + SZ_ACT)
#define O_X1        (O_CKV + SZ_CKV1)
#define O_X2        (O_X1 + SZ_D32)
#define SCRATCH_BYTES (O_X2 + SZ_D32)

__device__ __align__(1024) char g_scratch[SCRATCH_BYTES];

// ----------------------------------------------------------------------------
// PTX helpers (family-agnostic)
// ----------------------------------------------------------------------------
__device__ __forceinline__ uint32_t smem_u32(const void* p) {
    uint32_t a;
    asm("{ .reg .u64 t; cvta.to.shared.u64 t, %1; cvt.u32.u64 %0, t; }"
        : "=r"(a) : "l"(p));
    return a;
}
__device__ __forceinline__ void cpa16(uint32_t s, const void* g) {
    asm volatile("cp.async.cg.shared.global [%0], [%1], 16;" :: "r"(s), "l"(g));
}
#define CP_COMMIT() asm volatile("cp.async.commit_group;" ::: "memory")
#define CP_WAIT0() asm volatile("cp.async.wait_group 0;" ::: "memory")
#define CP_WAIT1() asm volatile("cp.async.wait_group 1;" ::: "memory")
#define CP_WAIT2() asm volatile("cp.async.wait_group 2;" ::: "memory")

__device__ __forceinline__ void ldm_x4(uint32_t* r, uint32_t addr) {
    asm volatile("ldmatrix.sync.aligned.m8n8.x4.shared.b16 {%0,%1,%2,%3}, [%4];"
        : "=r"(r[0]), "=r"(r[1]), "=r"(r[2]), "=r"(r[3]) : "r"(addr));
}
__device__ __forceinline__ void ldm_x4_t(uint32_t* r, uint32_t addr) {
    asm volatile("ldmatrix.sync.aligned.m8n8.x4.trans.shared.b16 {%0,%1,%2,%3}, [%4];"
        : "=r"(r[0]), "=r"(r[1]), "=r"(r[2]), "=r"(r[3]) : "r"(addr));
}
__device__ __forceinline__ void mma_f16(float* d, const uint32_t* a, const uint32_t* b) {
    asm volatile(
        "mma.sync.aligned.m16n8k16.row.col.f32.f16.f16.f32 "
        "{%0,%1,%2,%3}, {%4,%5,%6,%7}, {%8,%9}, {%0,%1,%2,%3};"
        : "+f"(d[0]), "+f"(d[1]), "+f"(d[2]), "+f"(d[3])
        : "r"(a[0]), "r"(a[1]), "r"(a[2]), "r"(a[3]), "r"(b[0]), "r"(b[1]));
}

__device__ __forceinline__ __half2 packh(float a, float b) {
    return __floats2half2_rn(a, b);
}
__device__ __forceinline__ uint32_t packu(float a, float b) {
    __half2 v = packh(a, b);
    return *(uint32_t*)&v;
}

// Fast exp on FFMA pipe (x <= 0 path), rel err ~2e-6
__device__ __forceinline__ float fexp(float x) {
    float z = x * 1.4426950408889634f;
    z = fmaxf(z, -120.0f);
    float zi = z + 12582912.0f;
    int i = __float_as_int(zi) - 0x4B400000;
    float f = z - (zi - 12582912.0f);
    float p = 1.3333558e-3f;
    p = fmaf(p, f, 9.6181291e-3f);
    p = fmaf(p, f, 5.5504109e-2f);
    p = fmaf(p, f, 2.4022651e-1f);
    p = fmaf(p, f, 6.9314718e-1f);
    p = fmaf(p, f, 1.0f);
    return p * __int_as_float((i + 127) << 23);
}

// ----------------------------------------------------------------------------
// Weight convert: fp32 -> fp16
// ----------------------------------------------------------------------------
__global__ __launch_bounds__(256)
void cvt_h_kernel(const float4* __restrict__ w, __half2* __restrict__ hi, int n4) {
    int i = blockIdx.x * 256 + threadIdx.x;
    if (i >= n4) return;
    const float4 v = w[i];
    hi[i * 2]     = packh(v.x, v.y);
    hi[i * 2 + 1] = packh(v.z, v.w);
}

// ffn_w1 interleave: dst row 2j = w1[j] (val), 2j+1 = w1[FF+j] (gate)
__global__ __launch_bounds__(256)
void cvt_h_ileave_kernel(const float* __restrict__ w, __half2* __restrict__ hi, int n4) {
    int i = blockIdx.x * 256 + threadIdx.x;
    if (i >= n4) return;
    const int row = i >> 8;
    const int col4 = (i & 255) * 4;
    const int srow = (row & 1) ? (FF_ + (row >> 1)) : (row >> 1);
    const float4 v = *(const float4*)(w + (size_t)srow * 1024 + col4);
    hi[i * 2]     = packh(v.x, v.y);
    hi[i * 2 + 1] = packh(v.z, v.w);
}

// ----------------------------------------------------------------------------
// LayerNorm -> fp16 plane
// ----------------------------------------------------------------------------
__global__ __launch_bounds__(256)
void ln_kernel(const float* __restrict__ x, const float* __restrict__ g,
               const float* __restrict__ b, __half* __restrict__ yh) {
    const int row = blockIdx.x;
    const int t = threadIdx.x;
    const float4 v = ((const float4*)(x + (size_t)row * D_))[t];

    __shared__ float red[8];
    __shared__ float stat[2];

    float s = v.x + v.y + v.z + v.w;
    #pragma unroll
    for (int o = 16; o; o >>= 1) s += __shfl_xor_sync(0xffffffffu, s, o);
    if ((t & 31) == 0) red[t >> 5] = s;
    __syncthreads();
    if (t == 0) {
        float s2 = 0.f;
        #pragma unroll
        for (int i = 0; i < 8; i++) s2 += red[i];
        stat[0] = s2 * (1.0f / D_);
    }
    __syncthreads();
    const float mu = stat[0];
    const float dx = v.x - mu, dy = v.y - mu, dz = v.z - mu, dw = v.w - mu;

    float q = dx * dx + dy * dy + dz * dz + dw * dw;
    #pragma unroll
    for (int o = 16; o; o >>= 1) q += __shfl_xor_sync(0xffffffffu, q, o);
    if ((t & 31) == 0) red[t >> 5] = q;
    __syncthreads();
    if (t == 0) {
        float s2 = 0.f;
        #pragma unroll
        for (int i = 0; i < 8; i++) s2 += red[i];
        stat[1] = rsqrtf(s2 * (1.0f / D_) + 1e-5f);
    }
    __syncthreads();
    const float rs = stat[1];

    const float4 gv = ((const float4*)g)[t];
    const float4 bv = ((const float4*)b)[t];
    const float o0 = dx * rs * gv.x + bv.x;
    const float o1 = dy * rs * gv.y + bv.y;
    const float o2 = dz * rs * gv.z + bv.z;
    const float o3 = dw * rs * gv.w + bv.w;
    const size_t base = (size_t)row * D_ + t * 4;
    *(__half2*)(yh + base)     = packh(o0, o1);
    *(__half2*)(yh + base + 2) = packh(o2, o3);
}

__device__ __forceinline__ float gelu_exact(float x) {
    return 0.5f * x * (1.0f + erff(x * 0.7071067811865476f));
}

// ----------------------------------------------------------------------------
// mma.sync 1-term fp16 GEMM: C[M,N] = A[M,K] @ W[N,K]^T (+epilogue)
// CTA tile 128x256, warp tile 64x64 (2x4 warps), K-chunk 64, 3-stage cp.async,
// register-fragment double buffering.
// EPI: 1 bias+res (fp32 out); 2 sigmoid(gate)*(..)+res (fp32 out);
//      3 bias only -> fp16 plane; 4 GEGLU (interleaved W) -> fp16 plane
// ----------------------------------------------------------------------------
#define TM 128
#define TN 256
#define KCH 64
#define RS 72
#define RSB (RS * 2)
#define APLANE_B (128 * RSB)        // 18432
#define WPLANE_B (256 * RSB)        // 36864
#define SA_A 0
#define SW_W APLANE_B
#define STAGE_B (APLANE_B + WPLANE_B)  // 55296
#define GEMM_SMEM (3 * STAGE_B)        // 165888

template <int EPI>
__global__ __launch_bounds__(256, 1)
void mma_gemm(const __half* __restrict__ A, const __half* __restrict__ W,
              const float* __restrict__ bias, const float* __restrict__ res,
              const float* __restrict__ gatep, float* __restrict__ C,
              __half* __restrict__ Ch,
              int N, int K, int wRowOff) {
    extern __shared__ char smem[];
    const uint32_t sb = smem_u32(smem);
    const int t = threadIdx.x;
    const int lane = t & 31;
    const int wid = t >> 5;
    const int wm = wid & 1;         // m half (64)
    const int wn = wid >> 1;        // n quarter (64)

    const int mBase = blockIdx.y * TM;
    const int nBase = blockIdx.x * TN;

    uint32_t sOffA[4], sOffW[8];
    size_t gOffA[4], gOffW[8];
    #pragma unroll
    for (int j = 0; j < 4; j++) {
        const int id = t + 256 * j;
        const int r = id >> 3;
        const int ch = id & 7;
        sOffA[j] = (uint32_t)r * RSB + ch * 16;
        gOffA[j] = ((size_t)(mBase + r) * K + ch * 8) * 2;
    }
    #pragma unroll
    for (int j = 0; j < 8; j++) {
        const int id = t + 256 * j;
        const int r = id >> 3;
        const int ch = id & 7;
        sOffW[j] = (uint32_t)r * RSB + ch * 16;
        gOffW[j] = ((size_t)(nBase + wRowOff + r) * K + ch * 8) * 2;
    }
    const char* pA = (const char*)A;
    const char* pW = (const char*)W;

    auto load_stage = [&](int c, int s) {
        const uint32_t sd = sb + s * STAGE_B;
        const size_t kb = (size_t)c * 128;
        #pragma unroll
        for (int j = 0; j < 4; j++)
            cpa16(sd + SA_A + sOffA[j], pA + gOffA[j] + kb);
        #pragma unroll
        for (int j = 0; j < 8; j++)
            cpa16(sd + SW_W + sOffW[j], pW + gOffW[j] + kb);
    };

    float acc[4][8][4];
    #pragma unroll
    for (int i = 0; i < 4; i++)
        #pragma unroll
        for (int j = 0; j < 8; j++)
            #pragma unroll
            for (int k = 0; k < 4; k++) acc[i][j][k] = 0.f;

    const int nch = K / KCH;
    load_stage(0, 0); CP_COMMIT();
    if (nch > 1) { load_stage(1, 1); CP_COMMIT(); }

    const uint32_t aRowOff = (uint32_t)(wm * 64 + (lane & 15)) * RSB
                           + ((lane >> 4) * 8) * 2;
    const uint32_t bRowOff = (uint32_t)(wn * 64 + (lane & 7) + ((lane >> 4) & 1) * 8) * RSB
                           + (((lane >> 3) & 1) * 8) * 2;

    uint32_t ah[2][4][4];
    uint32_t bw[2][8][2];

    int sidx = 0;
    for (int c = 0; c < nch; c++) {
        if (c + 2 < nch) {
            load_stage(c + 2, (sidx + 2) % 3);
            CP_COMMIT();
            CP_WAIT2();
        } else if (c + 1 < nch) {
            CP_WAIT1();
        } else {
            CP_WAIT0();
        }
        __syncthreads();

        const uint32_t sd = sb + sidx * STAGE_B;

        auto load_frags = [&](int kk, int buf) {
            #pragma unroll
            for (int mf = 0; mf < 4; mf++) {
                const uint32_t ad = sd + SA_A + aRowOff + (uint32_t)(mf * 16) * RSB + kk * 2;
                ldm_x4(ah[buf][mf], ad);
            }
            #pragma unroll
            for (int nf2 = 0; nf2 < 4; nf2++) {
                const uint32_t bd = sd + SW_W + bRowOff + (uint32_t)(nf2 * 16) * RSB + kk * 2;
                uint32_t r[4];
                ldm_x4(r, bd);
                bw[buf][nf2 * 2][0] = r[0]; bw[buf][nf2 * 2][1] = r[1];
                bw[buf][nf2 * 2 + 1][0] = r[2]; bw[buf][nf2 * 2 + 1][1] = r[3];
            }
        };

        load_frags(0, 0);
        #pragma unroll
        for (int s16 = 0; s16 < KCH / 16; s16++) {
            if (s16 + 1 < KCH / 16) load_frags((s16 + 1) * 16, (s16 + 1) & 1);
            const int buf = s16 & 1;
            #pragma unroll
            for (int mf = 0; mf < 4; mf++)
                #pragma unroll
                for (int nf = 0; nf < 8; nf++)
                    mma_f16(acc[mf][nf], ah[buf][mf], bw[buf][nf]);
        }
        __syncthreads();
        sidx = (sidx + 1) % 3;
    }

    // ---- epilogue ----
    float gs = 1.f;
    if (EPI == 2) gs = 1.f / (1.f + __expf(-gatep[0]));

    const int mWarp = mBase + wm * 64;
    const int nWarp = nBase + wn * 64;
    #pragma unroll
    for (int mf = 0; mf < 4; mf++) {
        const int r0 = mWarp + mf * 16 + (lane >> 2);
        #pragma unroll
        for (int nf = 0; nf < 8; nf++) {
            const int c0 = nWarp + nf * 8 + 2 * (lane & 3);
            if (EPI == 1 || EPI == 2) {
                const float b0 = bias[c0], b1 = bias[c0 + 1];
                float v0 = acc[mf][nf][0] + b0;
                float v1 = acc[mf][nf][1] + b1;
                float v2 = acc[mf][nf][2] + b0;
                float v3 = acc[mf][nf][3] + b1;
                if (EPI == 1) {
                    v0 += res[(size_t)r0 * N + c0];
                    v1 += res[(size_t)r0 * N + c0 + 1];
                    v2 += res[(size_t)(r0 + 8) * N + c0];
                    v3 += res[(size_t)(r0 + 8) * N + c0 + 1];
                } else {
                    v0 = gs * v0 + res[(size_t)r0 * N + c0];
                    v1 = gs * v1 + res[(size_t)r0 * N + c0 + 1];
                    v2 = gs * v2 + res[(size_t)(r0 + 8) * N + c0];
                    v3 = gs * v3 + res[(size_t)(r0 + 8) * N + c0 + 1];
                }
                *(float2*)(C + (size_t)r0 * N + c0) = make_float2(v0, v1);
                *(float2*)(C + (size_t)(r0 + 8) * N + c0) = make_float2(v2, v3);
            } else if (EPI == 3) {
                const float b0 = bias[c0], b1 = bias[c0 + 1];
                *(__half2*)(Ch + (size_t)r0 * N + c0) =
                    packh(acc[mf][nf][0] + b0, acc[mf][nf][1] + b1);
                *(__half2*)(Ch + (size_t)(r0 + 8) * N + c0) =
                    packh(acc[mf][nf][2] + b0, acc[mf][nf][3] + b1);
            } else {  // EPI == 4: GEGLU with interleaved W (even=val, odd=gate)
                const int jj = c0 >> 1;
                const int Nout = N >> 1;
                const float bv = bias[jj], bg = bias[FF_ + jj];
                const float va = acc[mf][nf][0] + bv;
                const float ga = acc[mf][nf][1] + bg;
                const float vb = acc[mf][nf][2] + bv;
                const float gb = acc[mf][nf][3] + bg;
                Ch[(size_t)r0 * Nout + jj] = __float2half_rn(va * gelu_exact(ga));
                Ch[(size_t)(r0 + 8) * Nout + jj] = __float2half_rn(vb * gelu_exact(gb));
            }
        }
    }
}

// ----------------------------------------------------------------------------
// Tensor-core flash attention (1-term fp16), HD=64, 64q x 64kv tiles.
// 128 threads (4 warps); warp w owns q rows [16w,16w+16).
// bias (optional) is fp32. Output fp16 plane with row stride D_.
// ----------------------------------------------------------------------------
#define FRSB 144
#define FPLANE (64 * FRSB)            // 9216
#define FSTAGE (2 * FPLANE)           // 18432 (K, V)
#define FQOFF  (2 * FSTAGE)           // 36864 (Q)
#define FLASH_SMEM (FQOFF + FPLANE)   // 46080

__global__ __launch_bounds__(128)
void flash_mma(const __half* __restrict__ Qh, int ldq,
               const __half* __restrict__ Kh, int ldk,
               const __half* __restrict__ Vh,
               const float* __restrict__ bias,
               __half* __restrict__ Oh,
               int Lq, int Lkv) {
    extern __shared__ char smem[];
    const uint32_t sb = smem_u32(smem);
    const int t = threadIdx.x, lane = t & 31, w = t >> 5;
    const int bh = blockIdx.y, b = bh >> 4, h = bh & 15;
    const int q0 = blockIdx.x * 64;

    // Q tile -> smem
    #pragma unroll
    for (int j = 0; j < 4; j++) {
        const int id = t + 128 * j, r = id >> 3, ch = id & 7;
        const size_t g = ((size_t)(b * Lq + q0 + r)) * ldq + h * 64 + ch * 8;
        cpa16(sb + FQOFF + (uint32_t)r * FRSB + ch * 16, (const char*)Qh + g * 2);
    }
    CP_COMMIT();

    auto load_kv = [&](int it, int s) {
        const uint32_t sd = sb + s * FSTAGE;
        const int k0 = it * 64;
        #pragma unroll
        for (int j = 0; j < 4; j++) {
            const int id = t + 128 * j, r = id >> 3, ch = id & 7;
            const size_t g = ((size_t)(b * Lkv + k0 + r)) * ldk + h * 64 + ch * 8;
            const uint32_t so = sd + (uint32_t)r * FRSB + ch * 16;
            cpa16(so,          (const char*)Kh + g * 2);
            cpa16(so + FPLANE, (const char*)Vh + g * 2);
        }
    };
    load_kv(0, 0); CP_COMMIT();

    uint32_t qf[4][4];
    float o_[8][4];
    #pragma unroll
    for (int i = 0; i < 8; i++)
        #pragma unroll
        for (int j = 0; j < 4; j++) o_[i][j] = 0.f;
    float m0 = -1e30f, m1 = -1e30f, l0 = 0.f, l1 = 0.f;
    const float invs = 0.125f;

    const int nt = Lkv / 64;
    for (int it = 0; it < nt; it++) {
        if (it + 1 < nt) { load_kv(it + 1, (it + 1) & 1); CP_COMMIT(); CP_WAIT1(); }
        else { CP_WAIT0(); }
        __syncthreads();
        const uint32_t sd = sb + (it & 1) * FSTAGE;

        if (it == 0) {
            #pragma unroll
            for (int kf = 0; kf < 4; kf++) {
                const uint32_t qa = sb + FQOFF
                    + (uint32_t)(w * 16 + (lane & 15)) * FRSB
                    + ((lane >> 4) * 8 + kf * 16) * 2;
                ldm_x4(qf[kf], qa);
            }
        }

        // ---- S = Q K^T ----
        float s_[8][4];
        #pragma unroll
        for (int i = 0; i < 8; i++)
            #pragma unroll
            for (int j = 0; j < 4; j++) s_[i][j] = 0.f;
        #pragma unroll
        for (int kf = 0; kf < 4; kf++) {
            #pragma unroll
            for (int g = 0; g < 4; g++) {
                const uint32_t ka = sd
                    + (uint32_t)(g * 16 + (lane & 7) + ((lane >> 4) & 1) * 8) * FRSB
                    + (((lane >> 3) & 1) * 8 + kf * 16) * 2;
                uint32_t rh[4];
                ldm_x4(rh, ka);
                mma_f16(s_[2 * g],     qf[kf], rh);
                mma_f16(s_[2 * g + 1], qf[kf], rh + 2);
            }
        }

        // ---- scale + bias ----
        if (bias) {
            const int k0 = it * 64;
            const float* bp = bias
                + ((size_t)bh * Lq + (q0 + w * 16 + (lane >> 2))) * Lkv
                + k0 + (lane & 3) * 2;
            #pragma unroll
            for (int nf = 0; nf < 8; nf++) {
                const float2 b0 = *(const float2*)(bp + nf * 8);
                const float2 b1 = *(const float2*)(bp + (size_t)8 * Lkv + nf * 8);
                s_[nf][0] = fmaf(s_[nf][0], invs, b0.x);
                s_[nf][1] = fmaf(s_[nf][1], invs, b0.y);
                s_[nf][2] = fmaf(s_[nf][2], invs, b1.x);
                s_[nf][3] = fmaf(s_[nf][3], invs, b1.y);
            }
        } else {
            #pragma unroll
            for (int nf = 0; nf < 8; nf++)
                #pragma unroll
                for (int i = 0; i < 4; i++) s_[nf][i] *= invs;
        }

        // ---- online softmax ----
        float mx0 = s_[0][0], mx1 = s_[0][2];
        #pragma unroll
        for (int nf = 0; nf < 8; nf++) {
            mx0 = fmaxf(mx0, fmaxf(s_[nf][0], s_[nf][1]));
            mx1 = fmaxf(mx1, fmaxf(s_[nf][2], s_[nf][3]));
        }
        mx0 = fmaxf(mx0, __shfl_xor_sync(0xffffffffu, mx0, 1));
        mx0 = fmaxf(mx0, __shfl_xor_sync(0xffffffffu, mx0, 2));
        mx1 = fmaxf(mx1, __shfl_xor_sync(0xffffffffu, mx1, 1));
        mx1 = fmaxf(mx1, __shfl_xor_sync(0xffffffffu, mx1, 2));
        const float mn0 = fmaxf(m0, mx0), mn1 = fmaxf(m1, mx1);
        const float sc0 = fexp(m0 - mn0), sc1 = fexp(m1 - mn1);
        m0 = mn0; m1 = mn1;
        float sum0 = 0.f, sum1 = 0.f;
        #pragma unroll
        for (int nf = 0; nf < 8; nf++) {
            s_[nf][0] = fexp(s_[nf][0] - mn0);
            s_[nf][1] = fexp(s_[nf][1] - mn0);
            s_[nf][2] = fexp(s_[nf][2] - mn1);
            s_[nf][3] = fexp(s_[nf][3] - mn1);
            sum0 += s_[nf][0] + s_[nf][1];
            sum1 += s_[nf][2] + s_[nf][3];
        }
        sum0 += __shfl_xor_sync(0xffffffffu, sum0, 1);
        sum0 += __shfl_xor_sync(0xffffffffu, sum0, 2);
        sum1 += __shfl_xor_sync(0xffffffffu, sum1, 1);
        sum1 += __shfl_xor_sync(0xffffffffu, sum1, 2);
        l0 = l0 * sc0 + sum0;
        l1 = l1 * sc1 + sum1;
        #pragma unroll
        for (int nf = 0; nf < 8; nf++) {
            o_[nf][0] *= sc0; o_[nf][1] *= sc0;
            o_[nf][2] *= sc1; o_[nf][3] *= sc1;
        }

        // ---- O += P V (P from regs, V via ldmatrix.trans) ----
        #pragma unroll
        for (int kf = 0; kf < 4; kf++) {
            uint32_t pa[4];
            pa[0] = packu(s_[2 * kf][0], s_[2 * kf][1]);
            pa[1] = packu(s_[2 * kf][2], s_[2 * kf][3]);
            pa[2] = packu(s_[2 * kf + 1][0], s_[2 * kf + 1][1]);
            pa[3] = packu(s_[2 * kf + 1][2], s_[2 * kf + 1][3]);
            #pragma unroll
            for (int g = 0; g < 4; g++) {
                const uint32_t va = sd + FPLANE
                    + (uint32_t)(kf * 16 + (lane & 15)) * FRSB
                    + ((lane >> 4) * 8 + g * 16) * 2;
                uint32_t rh[4];
                ldm_x4_t(rh, va);
                mma_f16(o_[2 * g],     pa, rh);
                mma_f16(o_[2 * g + 1], pa, rh + 2);
            }
        }
        __syncthreads();
    }

    // ---- normalize + store fp16 ----
    const float inv0 = 1.f / l0, inv1 = 1.f / l1;
    const int row0 = b * Lq + q0 + w * 16 + (lane >> 2);
    #pragma unroll
    for (int nf = 0; nf < 8; nf++) {
        const int col = h * 64 + nf * 8 + (lane & 3) * 2;
        *(__half2*)(Oh + (size_t)row0 * D_ + col) =
            packh(o_[nf][0] * inv0, o_[nf][1] * inv0);
        *(__half2*)(Oh + (size_t)(row0 + 8) * D_ + col) =
            packh(o_[nf][2] * inv1, o_[nf][3] * inv1);
    }
}

// ----------------------------------------------------------------------------
// Host orchestration — stream-fork overlap (graph-capturable fork/join).
// ----------------------------------------------------------------------------
extern "C" void kernel_launch(void* const* d_in, const int* in_sizes, int n_in,
                              void* d_out, int out_size) {
    const float* x          = (const float*)d_in[0];
    const float* alibi      = (const float*)d_in[1];
    const float* species    = (const float*)d_in[2];
    const float* norm1_g    = (const float*)d_in[3];
    const float* norm1_b    = (const float*)d_in[4];
    const float* sa_wqkv    = (const float*)d_in[5];
    const float* sa_bqkv    = (const float*)d_in[6];
    const float* sa_wo      = (const float*)d_in[7];
    const float* sa_bo      = (const float*)d_in[8];
    const float* ca_nq_g    = (const float*)d_in[9];
    const float* ca_nq_b    = (const float*)d_in[10];
    const float* ca_nkv_g   = (const float*)d_in[11];
    const float* ca_nkv_b   = (const float*)d_in[12];
    const float* ca_wqkv    = (const float*)d_in[13];
    const float* ca_bqkv    = (const float*)d_in[14];
    const float* ca_wo      = (const float*)d_in[15];
    const float* ca_bo      = (const float*)d_in[16];
    const float* gate_param = (const float*)d_in[17];
    const float* ffn_g      = (const float*)d_in[18];
    const float* ffn_b      = (const float*)d_in[19];
    const float* ffn_w1     = (const float*)d_in[20];
    const float* ffn_b1     = (const float*)d_in[21];
    const float* ffn_w2     = (const float*)d_in[22];
    const float* ffn_b2     = (const float*)d_in[23];
    float* out = (float*)d_out;

    char* S = nullptr;
    cudaGetSymbolAddress((void**)&S, g_scratch);
    #define HF(off) ((__half*)(S + (off)))
    #define F32(off) ((float*)(S + (off)))
    __half *wqkvs = HF(O_WQKVS), *wsao = HF(O_WSAO);
    __half *wqkvc = HF(O_WQKVC), *wcao = HF(O_WCAO);
    __half *wf1 = HF(O_WF1), *wf2 = HF(O_WF2);
    __half *lnb = HF(O_LN), *atb = HF(O_AT), *kvnb = HF(O_KVN);
    __half *ggb = HF(O_GG), *qkvb = HF(O_QKV);
    __half *cqb = HF(O_CQ), *ckvb = HF(O_CKV);
    float *x1 = F32(O_X1), *x2 = F32(O_X2);

    cudaFuncSetAttribute(mma_gemm<1>, cudaFuncAttributeMaxDynamicSharedMemorySize, GEMM_SMEM);
    cudaFuncSetAttribute(mma_gemm<2>, cudaFuncAttributeMaxDynamicSharedMemorySize, GEMM_SMEM);
    cudaFuncSetAttribute(mma_gemm<3>, cudaFuncAttributeMaxDynamicSharedMemorySize, GEMM_SMEM);
    cudaFuncSetAttribute(mma_gemm<4>, cudaFuncAttributeMaxDynamicSharedMemorySize, GEMM_SMEM);
    cudaFuncSetAttribute(flash_mma, cudaFuncAttributeMaxDynamicSharedMemorySize, FLASH_SMEM);

    cudaStream_t sA, sB;
    cudaStreamCreateWithFlags(&sA, cudaStreamNonBlocking);
    cudaStreamCreateWithFlags(&sB, cudaStreamNonBlocking);
    cudaEvent_t evFork, evQ, evW, evF, evB, evC;
    cudaEventCreateWithFlags(&evFork, cudaEventDisableTiming);
    cudaEventCreateWithFlags(&evQ,    cudaEventDisableTiming);
    cudaEventCreateWithFlags(&evW,    cudaEventDisableTiming);
    cudaEventCreateWithFlags(&evF,    cudaEventDisableTiming);
    cudaEventCreateWithFlags(&evB,    cudaEventDisableTiming);
    cudaEventCreateWithFlags(&evC,    cudaEventDisableTiming);

    auto cvt_on = [&](cudaStream_t st, const float* w, __half* h, size_t n) {
        cvt_h_kernel<<<(unsigned)((n / 4 + 255) / 256), 256, 0, st>>>(
            (const float4*)w, (__half2*)h, (int)(n / 4));
    };

    // ---- fork side stream A: QKV weights first, then the rest ----
    cudaEventRecord(evFork, 0);
    cudaStreamWaitEvent(sA, evFork, 0);
    cvt_on(sA, sa_wqkv, wqkvs, (size_t)3 * D_ * D_);
    cudaEventRecord(evQ, sA);           // joined before QKV GEMM
    cvt_on(sA, sa_wo,   wsao,  (size_t)D_ * D_);
    cvt_on(sA, ca_wqkv, wqkvc, (size_t)3 * D_ * D_);
    cvt_on(sA, ca_wo,   wcao,  (size_t)D_ * D_);
    ln_kernel<<<B_ * NS_, 256, 0, sA>>>(species, ca_nkv_g, ca_nkv_b, kvnb);
    cudaEventRecord(evW, sA);           // joined before SA-out GEMM
    cvt_on(sA, ffn_w2, wf2, (size_t)D_ * FF_);
    cvt_h_ileave_kernel<<<(2 * FF_ * D_ / 4 + 255) / 256, 256, 0, sA>>>(
        ffn_w1, (__half2*)wf1, 2 * FF_ * D_ / 4);
    cudaEventRecord(evF, sA);           // joined before FFN1 GEMM

    // ---- main stream: self-attention ----
    ln_kernel<<<M_, 256>>>(x, norm1_g, norm1_b, lnb);
    cudaStreamWaitEvent(0, evQ, 0);
    mma_gemm<3><<<dim3(3 * D_ / TN, M_ / TM), 256, GEMM_SMEM>>>(
        lnb, wqkvs, sa_bqkv, nullptr, nullptr, nullptr, qkvb, 3 * D_, D_, 0);
    flash_mma<<<dim3(L_ / 64, B_ * H_), 128, FLASH_SMEM>>>(
        qkvb, 3 * D_,
        qkvb + D_, 3 * D_,
        qkvb + 2 * D_,
        alibi, atb, L_, L_);
    cudaStreamWaitEvent(0, evW, 0);     // wsao/wqkvc/wcao/kvnb ready
    mma_gemm<1><<<dim3(D_ / TN, M_ / TM), 256, GEMM_SMEM>>>(
        atb, wsao, sa_bo, x, nullptr, x1, nullptr, D_, D_, 0);

    // ---- cross-attention (ckv GEMM overlapped on stream B) ----
    ln_kernel<<<M_, 256>>>(x1, ca_nq_g, ca_nq_b, lnb);
    cudaEventRecord(evB, 0);
    cudaStreamWaitEvent(sB, evB, 0);
    mma_gemm<3><<<dim3(2 * D_ / TN, (B_ * NS_) / TM), 256, GEMM_SMEM, sB>>>(
        kvnb, wqkvc, ca_bqkv + D_, nullptr, nullptr, nullptr, ckvb, 2 * D_, D_, D_);
    cudaEventRecord(evC, sB);
    mma_gemm<3><<<dim3(D_ / TN, M_ / TM), 256, GEMM_SMEM>>>(
        lnb, wqkvc, ca_bqkv, nullptr, nullptr, nullptr, cqb, D_, D_, 0);
    cudaStreamWaitEvent(0, evC, 0);
    flash_mma<<<dim3(L_ / 64, B_ * H_), 128, FLASH_SMEM>>>(
        cqb, D_,
        ckvb, 2 * D_,
        ckvb + D_,
        nullptr, atb, L_, NS_);
    mma_gemm<2><<<dim3(D_ / TN, M_ / TM), 256, GEMM_SMEM>>>(
        atb, wcao, ca_bo, x1, gate_param, x2, nullptr, D_, D_, 0);

    // ---- FFN (GEGLU fused into FFN1 epilogue) ----
    ln_kernel<<<M_, 256>>>(x2, ffn_g, ffn_b, lnb);
    cudaStreamWaitEvent(0, evF, 0);     // wf1/wf2 ready
    mma_gemm<4><<<dim3(2 * FF_ / TN, M_ / TM), 256, GEMM_SMEM>>>(
        lnb, wf1, ffn_b1, nullptr, nullptr, nullptr, ggb, 2 * FF_, D_, 0);
    mma_gemm<1><<<dim3(D_ / TN, M_ / TM), 256, GEMM_SMEM>>>(
        ggb, wf2, ffn_b2, x2, nullptr, out, nullptr, D_, FF_, 0);

    cudaEventDestroy(evFork);
    cudaEventDestroy(evQ);
    cudaEventDestroy(evW);
    cudaEventDestroy(evF);
    cudaEventDestroy(evB);
    cudaEventDestroy(evC);
    cudaStreamDestroy(sA);
    cudaStreamDestroy(sB);
}